// round 13
// baseline (speedup 1.0000x reference)
#include <cuda_runtime.h>
#include <cstdint>

// Problem constants: x(8,1024,256), adj(8,1024,1024), W(256,256), a(1,4,128)
#define Bb    8
#define Nn    1024
#define Cc    256
#define Hh    4
#define Dd    64
#define Mrows (Bb*Nn)   // 8192 token rows
#define HD    (Hh*Dd)   // 256

typedef unsigned long long u64;

// Scratch (static device arrays: no allocation allowed)
__device__ __align__(16) static float g_Wx[Mrows*HD];   // 8.4 MB
__device__ __align__(16) static float g_ei[Mrows*Hh];
__device__ __align__(16) static float g_ej[Mrows*Hh];

// ---------------- packed f32x2 helpers ----------------
__device__ __forceinline__ u64 pk2(float v) {
    u64 r; unsigned u = __float_as_uint(v);
    asm("mov.b64 %0, {%1, %1};" : "=l"(r) : "r"(u));
    return r;
}
__device__ __forceinline__ void fma2(u64& c, u64 a, u64 b) {
    asm("fma.rn.f32x2 %0, %1, %2, %3;" : "=l"(c) : "l"(a), "l"(b), "l"(c));
}

// ---------------- Kernel A: Wx = x @ W, fused e_i/e_j ----------------
// BM=64 (grid 128x4 = 512 CTAs -> 3.46 waves, less quantization waste than 256),
// BN=64 (== one head), BK=16, 256 threads, single-buffer (R10-proven layout).
// Thread (ty = t>>4 rows ty*4..+3; tx = t&15 cols tx*4..+3).
#define BM 64
#define BN 64
#define BK 16

__global__ __launch_bounds__(256) void gemm_eij_kernel(const float* __restrict__ x,
                                                       const float* __restrict__ W,
                                                       const float* __restrict__ a) {
    __shared__ __align__(16) float As[BK][BM + 2];  // transposed A, padded (66)
    __shared__ __align__(16) u64   Bs[BK][BN];      // packed pairs, layout [kk][q*16+s]
    __shared__ float s_ai[Dd], s_aj[Dd];

    const int t  = threadIdx.x;
    const int bm = blockIdx.x * BM;
    const int h  = blockIdx.y;         // head
    const int bn = h * BN;

    if (t < Dd) { s_ai[t] = a[h * 2 * Dd + t]; s_aj[t] = a[h * 2 * Dd + Dd + t]; }

    const int tx   = t & 15;     // 4 cols each
    const int ty   = t >> 4;     // 0..15 -> 4 rows each
    const int arow = t >> 2;     // A-loader row 0..63
    const int akc  = (t & 3) * 4;
    const int brow = t >> 4;     // B-loader k-row 0..15
    const int bs   = t & 15;     // B-loader col group

    u64 acc[2][4];   // [row-pair rp][col q]: rows ty*4+2rp, +1
#pragma unroll
    for (int i = 0; i < 2; i++)
#pragma unroll
        for (int j = 0; j < 4; j++) acc[i][j] = 0ull;

    for (int k0 = 0; k0 < Cc; k0 += BK) {
        // A tile: 64x16, each thread 1 float4, stores transposed
        {
            float4 v = *reinterpret_cast<const float4*>(x + (size_t)(bm + arow) * Cc + k0 + akc);
            As[akc + 0][arow] = v.x; As[akc + 1][arow] = v.y;
            As[akc + 2][arow] = v.z; As[akc + 3][arow] = v.w;
        }
        // B tile: 16x64, pre-packed + transposed: logical col d=bs*4+q -> Bs[kr][q*16+bs]
        {
            float4 v = *reinterpret_cast<const float4*>(W + (size_t)(k0 + brow) * HD + bn + bs * 4);
            Bs[brow][0 * 16 + bs] = pk2(v.x);
            Bs[brow][1 * 16 + bs] = pk2(v.y);
            Bs[brow][2 * 16 + bs] = pk2(v.z);
            Bs[brow][3 * 16 + bs] = pk2(v.w);
        }
        __syncthreads();

#pragma unroll
        for (int kk = 0; kk < BK; kk++) {
            const float* ap = &As[kk][ty * 4];
            const u64 a0 = *reinterpret_cast<const u64*>(ap + 0);
            const u64 a1 = *reinterpret_cast<const u64*>(ap + 2);
            const u64 b0 = Bs[kk][0 * 16 + tx];
            const u64 b1 = Bs[kk][1 * 16 + tx];
            const u64 b2 = Bs[kk][2 * 16 + tx];
            const u64 b3 = Bs[kk][3 * 16 + tx];
            fma2(acc[0][0], a0, b0); fma2(acc[0][1], a0, b1);
            fma2(acc[0][2], a0, b2); fma2(acc[0][3], a0, b3);
            fma2(acc[1][0], a1, b0); fma2(acc[1][1], a1, b1);
            fma2(acc[1][2], a1, b2); fma2(acc[1][3], a1, b3);
        }
        __syncthreads();
    }

    // Epilogue: STG.128 rows of Wx + fused per-head e_i/e_j partials.
    // acc[rp][q].x -> row ty*4+2rp, col tx*4+q; .y -> row +1.
    float pi[4], pj[4];
#pragma unroll
    for (int rp = 0; rp < 2; rp++) {
        const int r0 = bm + ty * 4 + rp * 2;
        float4 o0, o1;
        float2 v0 = *reinterpret_cast<float2*>(&acc[rp][0]);
        float2 v1 = *reinterpret_cast<float2*>(&acc[rp][1]);
        float2 v2 = *reinterpret_cast<float2*>(&acc[rp][2]);
        float2 v3 = *reinterpret_cast<float2*>(&acc[rp][3]);
        o0.x = v0.x; o0.y = v1.x; o0.z = v2.x; o0.w = v3.x;
        o1.x = v0.y; o1.y = v1.y; o1.z = v2.y; o1.w = v3.y;
        *reinterpret_cast<float4*>(&g_Wx[(size_t)r0 * HD + bn + tx * 4])       = o0;
        *reinterpret_cast<float4*>(&g_Wx[(size_t)(r0 + 1) * HD + bn + tx * 4]) = o1;
        const int d0 = tx * 4;
        pi[rp*2+0] = o0.x*s_ai[d0] + o0.y*s_ai[d0+1] + o0.z*s_ai[d0+2] + o0.w*s_ai[d0+3];
        pj[rp*2+0] = o0.x*s_aj[d0] + o0.y*s_aj[d0+1] + o0.z*s_aj[d0+2] + o0.w*s_aj[d0+3];
        pi[rp*2+1] = o1.x*s_ai[d0] + o1.y*s_ai[d0+1] + o1.z*s_ai[d0+2] + o1.w*s_ai[d0+3];
        pj[rp*2+1] = o1.x*s_aj[d0] + o1.y*s_aj[d0+1] + o1.z*s_aj[d0+2] + o1.w*s_aj[d0+3];
    }
    // reduce across the 16 tx lanes (offsets 1..8 stay within each 16-lane half)
#pragma unroll
    for (int o = 1; o < 16; o <<= 1) {
#pragma unroll
        for (int r = 0; r < 4; r++) {
            pi[r] += __shfl_xor_sync(0xffffffffu, pi[r], o);
            pj[r] += __shfl_xor_sync(0xffffffffu, pj[r], o);
        }
    }
    if (tx == 0) {
#pragma unroll
        for (int r = 0; r < 4; r++) {
            const int row = bm + ty * 4 + ((r >> 1) * 2) + (r & 1);  // = ty*4 + r
            g_ei[row * Hh + h] = pi[r];
            g_ej[row * Hh + h] = pj[r];
        }
    }
}

// ---------------- Kernel B: sparse masked softmax + aggregation ----------------
// One block per (b, n). Deterministic compaction; single-pass exp (logits bounded,
// fp32-safe). Gather: LDG.128, 64 threads/row, 4 slots; per-head packed (w, offset)
// float2 in smem so the inner loop is 1 LDS.64 per neighbor.
#define CAP 384   // neighbor-list capacity (binomial(1024,.05) max ~86; huge margin)

__global__ __launch_bounds__(256) void attn_kernel(const float* __restrict__ adj,
                                                   float* __restrict__ out) {
    __shared__ int   s_idx[Nn];
    __shared__ __align__(16) float2 s_pk[Hh][CAP];   // (w_h, bitcast(float4 offset))
    __shared__ int   s_wcnt[8];
    __shared__ float s_red[8 * Hh];
    __shared__ float s_ei[Hh];
    __shared__ __align__(16) float4 s_part[3][64];

    const int t    = threadIdx.x;
    const int bid  = blockIdx.x;        // = b*1024 + n
    const int b    = bid >> 10;
    const int n    = bid & (Nn - 1);
    const int lane = t & 31;
    const int w    = t >> 5;

    if (t < Hh) s_ei[t] = g_ei[bid * Hh + t];

    // --- Phase 1: compact neighbor list (adj!=0 || j==n), sorted, no atomics ---
    const float4 av = reinterpret_cast<const float4*>(adj + (size_t)bid * Nn)[t];
    const int j0 = 4 * t;
    const int p0 = (av.x != 0.f) | (j0 == n);
    const int p1 = (av.y != 0.f) | (j0 + 1 == n);
    const int p2 = (av.z != 0.f) | (j0 + 2 == n);
    const int p3 = (av.w != 0.f) | (j0 + 3 == n);
    const int cnt = p0 + p1 + p2 + p3;
    int incl = cnt;
#pragma unroll
    for (int o = 1; o < 32; o <<= 1) {
        int v = __shfl_up_sync(0xffffffffu, incl, o);
        if (lane >= o) incl += v;
    }
    if (lane == 31) s_wcnt[w] = incl;
    __syncthreads();
    int base = 0, total = 0;
#pragma unroll
    for (int ww = 0; ww < 8; ++ww) {
        const int c = s_wcnt[ww];
        total += c;
        if (ww < w) base += c;
    }
    int off = base + incl - cnt;
    if (p0) s_idx[off++] = j0;
    if (p1) s_idx[off++] = j0 + 1;
    if (p2) s_idx[off++] = j0 + 2;
    if (p3) s_idx[off++] = j0 + 3;
    __syncthreads();

    // --- Phase 2: w = exp(leaky(ei+ej)); per-head sums; pack (w, float4-offset) ---
    const float ei0 = s_ei[0], ei1 = s_ei[1], ei2 = s_ei[2], ei3 = s_ei[3];
    float s0 = 0.f, s1 = 0.f, s2 = 0.f, s3 = 0.f;
    for (int k = t; k < total; k += 256) {
        const int j = s_idx[k];
        float4 ej = *reinterpret_cast<const float4*>(g_ej + ((size_t)(b << 10) + j) * Hh);
        float e0 = ei0 + ej.x; e0 = e0 > 0.f ? e0 : 0.2f * e0;
        float e1 = ei1 + ej.y; e1 = e1 > 0.f ? e1 : 0.2f * e1;
        float e2 = ei2 + ej.z; e2 = e2 > 0.f ? e2 : 0.2f * e2;
        float e3 = ei3 + ej.w; e3 = e3 > 0.f ? e3 : 0.2f * e3;
        e0 = __expf(e0); e1 = __expf(e1); e2 = __expf(e2); e3 = __expf(e3);
        const float fo = __int_as_float(j << 6);   // float4 units: j * (HD/4)
        s_pk[0][k] = make_float2(e0, fo);
        s_pk[1][k] = make_float2(e1, fo);
        s_pk[2][k] = make_float2(e2, fo);
        s_pk[3][k] = make_float2(e3, fo);
        s0 += e0; s1 += e1; s2 += e2; s3 += e3;
    }
#pragma unroll
    for (int o = 16; o >= 1; o >>= 1) {
        s0 += __shfl_xor_sync(0xffffffffu, s0, o);
        s1 += __shfl_xor_sync(0xffffffffu, s1, o);
        s2 += __shfl_xor_sync(0xffffffffu, s2, o);
        s3 += __shfl_xor_sync(0xffffffffu, s3, o);
    }
    if (lane == 0) { s_red[w*4+0]=s0; s_red[w*4+1]=s1; s_red[w*4+2]=s2; s_red[w*4+3]=s3; }
    __syncthreads();

    // --- Phase 3: gather. slot = t>>6 walks neighbors k = slot, slot+4, ...;
    //     u = t&63 is the float4 channel index (head h = u>>4). ---
    const int slot = t >> 6;
    const int u    = t & 63;
    const int h    = u >> 4;

    const float4* basep = reinterpret_cast<const float4*>(g_Wx + ((size_t)(b << 10)) * HD) + u;
    const float2* pkh   = s_pk[h];
    u64 aA = 0ull, aB = 0ull, aC = 0ull, aD = 0ull;
    int k = slot;
    for (; k + 4 < total; k += 8) {
        const float2 pA = pkh[k];
        const float2 pB = pkh[k + 4];
        const u64 w0 = pk2(pA.x);
        const u64 w1 = pk2(pB.x);
        const float4 f0 = basep[__float_as_int(pA.y)];
        const float4 f1 = basep[__float_as_int(pB.y)];
        const u64* q0 = reinterpret_cast<const u64*>(&f0);
        const u64* q1 = reinterpret_cast<const u64*>(&f1);
        fma2(aA, q0[0], w0); fma2(aB, q0[1], w0);
        fma2(aC, q1[0], w1); fma2(aD, q1[1], w1);
    }
    for (; k < total; k += 4) {
        const float2 pA = pkh[k];
        const u64 wv = pk2(pA.x);
        const float4 f = basep[__float_as_int(pA.y)];
        const u64* q = reinterpret_cast<const u64*>(&f);
        fma2(aA, q[0], wv); fma2(aB, q[1], wv);
    }
    float2 vA = *reinterpret_cast<float2*>(&aA);
    float2 vB = *reinterpret_cast<float2*>(&aB);
    float2 vC = *reinterpret_cast<float2*>(&aC);
    float2 vD = *reinterpret_cast<float2*>(&aD);
    float4 part;
    part.x = vA.x + vC.x; part.y = vA.y + vC.y;
    part.z = vB.x + vD.x; part.w = vB.y + vD.y;

    if (slot > 0) s_part[slot - 1][u] = part;
    __syncthreads();
    if (slot == 0) {
        float gsum = 0.f;
#pragma unroll
        for (int ww = 0; ww < 8; ww++) gsum += s_red[ww*4 + h];
        const float4 q1 = s_part[0][u];
        const float4 q2 = s_part[1][u];
        const float4 q3 = s_part[2][u];
        float4 res;
        res.x = ((part.x + q1.x) + (q2.x + q3.x)) / gsum;
        res.y = ((part.y + q1.y) + (q2.y + q3.y)) / gsum;
        res.z = ((part.z + q1.z) + (q2.z + q3.z)) / gsum;
        res.w = ((part.w + q1.w) + (q2.w + q3.w)) / gsum;
        reinterpret_cast<float4*>(out)[(size_t)bid * 64 + u] = res;
    }
}

// ---------------- launch ----------------
extern "C" void kernel_launch(void* const* d_in, const int* in_sizes, int n_in,
                              void* d_out, int out_size) {
    const float* x   = (const float*)d_in[0];  // (8,1024,256)
    const float* adj = (const float*)d_in[1];  // (8,1024,1024)
    const float* W   = (const float*)d_in[2];  // (256,256)
    const float* a   = (const float*)d_in[3];  // (1,4,128)
    float* out = (float*)d_out;                // (8,1024,256)

    (void)in_sizes; (void)n_in; (void)out_size;

    gemm_eij_kernel<<<dim3(Mrows / BM, Hh), 256>>>(x, W, a);
    attn_kernel<<<Mrows, 256>>>(adj, out);
}

// round 15
// speedup vs baseline: 1.8160x; 1.8160x over previous
#include <cuda_runtime.h>
#include <cstdint>

// Problem constants: x(8,1024,256), adj(8,1024,1024), W(256,256), a(1,4,128)
#define Bb    8
#define Nn    1024
#define Cc    256
#define Hh    4
#define Dd    64
#define Mrows (Bb*Nn)   // 8192 token rows
#define HD    (Hh*Dd)   // 256

typedef unsigned long long u64;

// Scratch (static device arrays: no allocation allowed)
__device__ __align__(16) static float g_Wx[Mrows*HD];   // 8.4 MB
__device__ __align__(16) static float g_ei[Mrows*Hh];
__device__ __align__(16) static float g_ej[Mrows*Hh];

// ---------------- packed f32x2 helpers ----------------
__device__ __forceinline__ u64 pk2(float v) {
    u64 r; unsigned u = __float_as_uint(v);
    asm("mov.b64 %0, {%1, %1};" : "=l"(r) : "r"(u));
    return r;
}
__device__ __forceinline__ void fma2(u64& c, u64 a, u64 b) {
    asm("fma.rn.f32x2 %0, %1, %2, %3;" : "=l"(c) : "l"(a), "l"(b), "l"(c));
}

// ---------------- Kernel A: Wx = x @ W, fused e_i/e_j ----------------
// R10-measured best (implied 38.1us). BM=128, BN=64 (== one head), BK=16.
// Single-buffer; B tile pre-packed as f32x2 u64, stored transposed so inner-loop
// B reads are conflict-free LDS.64 broadcasts. 16 fma2 : 8 LDS per kk.
#define BM 128
#define BN 64
#define BK 16

__global__ __launch_bounds__(256) void gemm_eij_kernel(const float* __restrict__ x,
                                                       const float* __restrict__ W,
                                                       const float* __restrict__ a) {
    __shared__ __align__(16) float As[BK][BM + 2];  // transposed A, padded
    __shared__ __align__(16) u64   Bs[BK][BN];      // packed pairs, layout [kk][q*16+tx]
    __shared__ float s_ai[Dd], s_aj[Dd];

    const int t  = threadIdx.x;
    const int bm = blockIdx.x * BM;
    const int h  = blockIdx.y;         // head: block covers cols [h*64, h*64+64)
    const int bn = h * BN;

    if (t < Dd) { s_ai[t] = a[h * 2 * Dd + t]; s_aj[t] = a[h * 2 * Dd + Dd + t]; }

    const int tx   = t & 15;     // 4 cols each
    const int ty   = t >> 4;     // 8 rows each
    const int lrow = t >> 1;     // A-loader row 0..127
    const int lk   = (t & 1) * 8;
    const int bkr  = t >> 4;     // B-loader k-row 0..15
    const int btx  = t & 15;     // B-loader col group

    u64 acc[4][4];
#pragma unroll
    for (int i = 0; i < 4; i++)
#pragma unroll
        for (int j = 0; j < 4; j++) acc[i][j] = 0ull;

    for (int k0 = 0; k0 < Cc; k0 += BK) {
        // A tile: 128x16, each thread loads 8 floats, stores transposed
        {
            const float* src = x + (size_t)(bm + lrow) * Cc + k0 + lk;
            float4 v0 = *reinterpret_cast<const float4*>(src);
            float4 v1 = *reinterpret_cast<const float4*>(src + 4);
            As[lk + 0][lrow] = v0.x; As[lk + 1][lrow] = v0.y;
            As[lk + 2][lrow] = v0.z; As[lk + 3][lrow] = v0.w;
            As[lk + 4][lrow] = v1.x; As[lk + 5][lrow] = v1.y;
            As[lk + 6][lrow] = v1.z; As[lk + 7][lrow] = v1.w;
        }
        // B tile: 16x64, pre-packed + transposed: logical col d=btx*4+q -> Bs[kr][q*16+btx]
        {
            float4 v = *reinterpret_cast<const float4*>(W + (size_t)(k0 + bkr) * HD + bn + btx * 4);
            Bs[bkr][0 * 16 + btx] = pk2(v.x);
            Bs[bkr][1 * 16 + btx] = pk2(v.y);
            Bs[bkr][2 * 16 + btx] = pk2(v.z);
            Bs[bkr][3 * 16 + btx] = pk2(v.w);
        }
        __syncthreads();

#pragma unroll
        for (int kk = 0; kk < BK; kk++) {
            const float* ap = &As[kk][ty * 8];
            u64 ar0 = *reinterpret_cast<const u64*>(ap + 0);
            u64 ar1 = *reinterpret_cast<const u64*>(ap + 2);
            u64 ar2 = *reinterpret_cast<const u64*>(ap + 4);
            u64 ar3 = *reinterpret_cast<const u64*>(ap + 6);
            u64 b0 = Bs[kk][0 * 16 + tx];
            u64 b1 = Bs[kk][1 * 16 + tx];
            u64 b2 = Bs[kk][2 * 16 + tx];
            u64 b3 = Bs[kk][3 * 16 + tx];
            fma2(acc[0][0],ar0,b0); fma2(acc[0][1],ar0,b1); fma2(acc[0][2],ar0,b2); fma2(acc[0][3],ar0,b3);
            fma2(acc[1][0],ar1,b0); fma2(acc[1][1],ar1,b1); fma2(acc[1][2],ar1,b2); fma2(acc[1][3],ar1,b3);
            fma2(acc[2][0],ar2,b0); fma2(acc[2][1],ar2,b1); fma2(acc[2][2],ar2,b2); fma2(acc[2][3],ar2,b3);
            fma2(acc[3][0],ar3,b0); fma2(acc[3][1],ar3,b1); fma2(acc[3][2],ar3,b2); fma2(acc[3][3],ar3,b3);
        }
        __syncthreads();
    }

    // Epilogue: write Wx and fused per-head e_i/e_j partials (col = tx*4+q).
    float pi[4][2], pj[4][2];
#pragma unroll
    for (int rp = 0; rp < 4; rp++) {
        const int r = bm + ty * 8 + rp * 2;
        float six = 0.f, siy = 0.f, sjx = 0.f, sjy = 0.f;
#pragma unroll
        for (int q = 0; q < 4; q++) {
            float2 v = *reinterpret_cast<float2*>(&acc[rp][q]);
            const int d = tx * 4 + q;
            g_Wx[(size_t)r * HD + bn + d]       = v.x;
            g_Wx[(size_t)(r + 1) * HD + bn + d] = v.y;
            six += v.x * s_ai[d]; sjx += v.x * s_aj[d];
            siy += v.y * s_ai[d]; sjy += v.y * s_aj[d];
        }
        pi[rp][0] = six; pi[rp][1] = siy;
        pj[rp][0] = sjx; pj[rp][1] = sjy;
    }
#pragma unroll
    for (int rp = 0; rp < 4; rp++) {
#pragma unroll
        for (int o = 1; o < 16; o <<= 1) {
            pi[rp][0] += __shfl_xor_sync(0xffffffffu, pi[rp][0], o);
            pi[rp][1] += __shfl_xor_sync(0xffffffffu, pi[rp][1], o);
            pj[rp][0] += __shfl_xor_sync(0xffffffffu, pj[rp][0], o);
            pj[rp][1] += __shfl_xor_sync(0xffffffffu, pj[rp][1], o);
        }
    }
    if (tx == 0) {
#pragma unroll
        for (int rp = 0; rp < 4; rp++) {
            const int r = bm + ty * 8 + rp * 2;
            g_ei[r * Hh + h]       = pi[rp][0];
            g_ei[(r + 1) * Hh + h] = pi[rp][1];
            g_ej[r * Hh + h]       = pj[rp][0];
            g_ej[(r + 1) * Hh + h] = pj[rp][1];
        }
    }
}

// ---------------- Kernel B: sparse masked softmax + aggregation ----------------
// R11-measured best (43.6us). One block per (b, n). Deterministic compaction;
// single-pass exp (logits bounded, fp32-safe). Gather: LDG.128, 64 threads/row,
// 4 neighbor slots, fma2 accumulate, cross-slot smem reduce. gsum only in epilogue.
__global__ __launch_bounds__(256) void attn_kernel(const float* __restrict__ adj,
                                                   float* __restrict__ out) {
    __shared__ int   s_idx[Nn];
    __shared__ __align__(16) float s_w[Nn * Hh];
    __shared__ int   s_wcnt[8];
    __shared__ float s_red[8 * Hh];
    __shared__ float s_ei[Hh];
    __shared__ __align__(16) float4 s_part[3][64];

    const int t    = threadIdx.x;
    const int bid  = blockIdx.x;        // = b*1024 + n
    const int b    = bid >> 10;
    const int n    = bid & (Nn - 1);
    const int lane = t & 31;
    const int w    = t >> 5;

    if (t < Hh) s_ei[t] = g_ei[bid * Hh + t];

    // --- Phase 1: compact neighbor list (adj!=0 || j==n), sorted, no atomics ---
    const float4 av = reinterpret_cast<const float4*>(adj + (size_t)bid * Nn)[t];
    const int j0 = 4 * t;
    const int p0 = (av.x != 0.f) | (j0 == n);
    const int p1 = (av.y != 0.f) | (j0 + 1 == n);
    const int p2 = (av.z != 0.f) | (j0 + 2 == n);
    const int p3 = (av.w != 0.f) | (j0 + 3 == n);
    const int cnt = p0 + p1 + p2 + p3;
    int incl = cnt;
#pragma unroll
    for (int o = 1; o < 32; o <<= 1) {
        int v = __shfl_up_sync(0xffffffffu, incl, o);
        if (lane >= o) incl += v;
    }
    if (lane == 31) s_wcnt[w] = incl;
    __syncthreads();
    int base = 0, total = 0;
#pragma unroll
    for (int ww = 0; ww < 8; ++ww) {
        const int c = s_wcnt[ww];
        total += c;
        if (ww < w) base += c;
    }
    int off = base + incl - cnt;
    if (p0) s_idx[off++] = j0;
    if (p1) s_idx[off++] = j0 + 1;
    if (p2) s_idx[off++] = j0 + 2;
    if (p3) s_idx[off++] = j0 + 3;
    __syncthreads();

    // --- Phase 2: w = exp(leaky(ei+ej)); per-head sums; rewrite s_idx to
    //     float4-row offsets (j * 64) for the gather. ---
    const float ei0 = s_ei[0], ei1 = s_ei[1], ei2 = s_ei[2], ei3 = s_ei[3];
    float s0 = 0.f, s1 = 0.f, s2 = 0.f, s3 = 0.f;
    for (int k = t; k < total; k += 256) {
        const int j = s_idx[k];
        float4 ej = *reinterpret_cast<const float4*>(g_ej + ((size_t)(b << 10) + j) * Hh);
        float e0 = ei0 + ej.x; e0 = e0 > 0.f ? e0 : 0.2f * e0;
        float e1 = ei1 + ej.y; e1 = e1 > 0.f ? e1 : 0.2f * e1;
        float e2 = ei2 + ej.z; e2 = e2 > 0.f ? e2 : 0.2f * e2;
        float e3 = ei3 + ej.w; e3 = e3 > 0.f ? e3 : 0.2f * e3;
        e0 = __expf(e0); e1 = __expf(e1); e2 = __expf(e2); e3 = __expf(e3);
        reinterpret_cast<float4*>(s_w)[k] = make_float4(e0, e1, e2, e3);
        s0 += e0; s1 += e1; s2 += e2; s3 += e3;
        s_idx[k] = j << 6;   // float4 units: j * (HD/4)
    }
#pragma unroll
    for (int o = 16; o >= 1; o >>= 1) {
        s0 += __shfl_xor_sync(0xffffffffu, s0, o);
        s1 += __shfl_xor_sync(0xffffffffu, s1, o);
        s2 += __shfl_xor_sync(0xffffffffu, s2, o);
        s3 += __shfl_xor_sync(0xffffffffu, s3, o);
    }
    if (lane == 0) { s_red[w*4+0]=s0; s_red[w*4+1]=s1; s_red[w*4+2]=s2; s_red[w*4+3]=s3; }
    __syncthreads();

    // --- Phase 3: gather. slot = t>>6 walks neighbors k = slot, slot+4, ...;
    //     u = t&63 is the float4 channel index (head h = u>>4). ---
    const int slot = t >> 6;
    const int u    = t & 63;
    const int h    = u >> 4;

    const float4* basep = reinterpret_cast<const float4*>(g_Wx + ((size_t)(b << 10)) * HD) + u;
    u64 aA = 0ull, aB = 0ull, aC = 0ull, aD = 0ull;
    int k = slot;
    for (; k + 4 < total; k += 8) {
        const int o0 = s_idx[k], o1 = s_idx[k + 4];
        const u64 w0 = pk2(s_w[k * 4 + h]);
        const u64 w1 = pk2(s_w[(k + 4) * 4 + h]);
        const float4 f0 = basep[o0];
        const float4 f1 = basep[o1];
        const u64* q0 = reinterpret_cast<const u64*>(&f0);
        const u64* q1 = reinterpret_cast<const u64*>(&f1);
        fma2(aA, q0[0], w0); fma2(aB, q0[1], w0);
        fma2(aC, q1[0], w1); fma2(aD, q1[1], w1);
    }
    for (; k < total; k += 4) {
        const u64 wv = pk2(s_w[k * 4 + h]);
        const float4 f = basep[s_idx[k]];
        const u64* q = reinterpret_cast<const u64*>(&f);
        fma2(aA, q[0], wv); fma2(aB, q[1], wv);
    }
    float2 vA = *reinterpret_cast<float2*>(&aA);
    float2 vB = *reinterpret_cast<float2*>(&aB);
    float2 vC = *reinterpret_cast<float2*>(&aC);
    float2 vD = *reinterpret_cast<float2*>(&aD);
    float4 part;
    part.x = vA.x + vC.x; part.y = vA.y + vC.y;
    part.z = vB.x + vD.x; part.w = vB.y + vD.y;

    if (slot > 0) s_part[slot - 1][u] = part;
    __syncthreads();
    if (slot == 0) {
        float gsum = 0.f;
#pragma unroll
        for (int ww = 0; ww < 8; ww++) gsum += s_red[ww*4 + h];
        const float4 q1 = s_part[0][u];
        const float4 q2 = s_part[1][u];
        const float4 q3 = s_part[2][u];
        float4 res;
        res.x = ((part.x + q1.x) + (q2.x + q3.x)) / gsum;
        res.y = ((part.y + q1.y) + (q2.y + q3.y)) / gsum;
        res.z = ((part.z + q1.z) + (q2.z + q3.z)) / gsum;
        res.w = ((part.w + q1.w) + (q2.w + q3.w)) / gsum;
        reinterpret_cast<float4*>(out)[(size_t)bid * 64 + u] = res;
    }
}

// ---------------- launch ----------------
extern "C" void kernel_launch(void* const* d_in, const int* in_sizes, int n_in,
                              void* d_out, int out_size) {
    const float* x   = (const float*)d_in[0];  // (8,1024,256)
    const float* adj = (const float*)d_in[1];  // (8,1024,1024)
    const float* W   = (const float*)d_in[2];  // (256,256)
    const float* a   = (const float*)d_in[3];  // (1,4,128)
    float* out = (float*)d_out;                // (8,1024,256)

    (void)in_sizes; (void)n_in; (void)out_size;

    gemm_eij_kernel<<<dim3(Mrows / BM, Hh), 256>>>(x, W, a);
    attn_kernel<<<Mrows, 256>>>(adj, out);
}